// round 10
// baseline (speedup 1.0000x reference)
#include <cuda_runtime.h>
#include <cuda_bf16.h>
#include <cstdint>

#define BATCH 8
#define SEQ   2048
#define DIM   512

// Scratch
__device__ float g_M[BATCH * DIM * DIM];    // M = K^T V   [b][i][j]   8 MiB
__device__ float g_Qt[BATCH * DIM * SEQ];   // Q^T         [b][i][q]  32 MiB
__device__ int g_vlen_is64;

// ---------------------------------------------------------------------------
// tf32 helpers
// ---------------------------------------------------------------------------
__device__ __forceinline__ void split_tf32(float x, uint32_t& h, uint32_t& l) {
    asm("cvt.rna.tf32.f32 %0, %1;" : "=r"(h) : "f"(x));
    float r = x - __uint_as_float(h);
    asm("cvt.rna.tf32.f32 %0, %1;" : "=r"(l) : "f"(r));
}

__device__ __forceinline__ void mma_tf32(float* c, const uint32_t* a, const uint32_t* b) {
    asm volatile(
        "mma.sync.aligned.m16n8k8.row.col.f32.tf32.tf32.f32 "
        "{%0,%1,%2,%3}, {%4,%5,%6,%7}, {%8,%9}, {%0,%1,%2,%3};"
        : "+f"(c[0]), "+f"(c[1]), "+f"(c[2]), "+f"(c[3])
        : "r"(a[0]), "r"(a[1]), "r"(a[2]), "r"(a[3]), "r"(b[0]), "r"(b[1]));
}

// ---------------------------------------------------------------------------
// valid_len dtype detector (int64 vs int32) — proven R4
// ---------------------------------------------------------------------------
__global__ void detect_vlen_kernel(const unsigned long long* __restrict__ v) {
    __shared__ int bad;
    if (threadIdx.x == 0) bad = 0;
    __syncthreads();
    for (int i = threadIdx.x; i < 1024; i += blockDim.x)
        if (v[i] >= 512ull) atomicOr(&bad, 1);
    __syncthreads();
    if (threadIdx.x == 0) g_vlen_is64 = bad ? 0 : 1;
}

// ---------------------------------------------------------------------------
// Q transpose: Q [B,SEQ,DIM] -> g_Qt [B,DIM,SEQ]  (32x32 smem tiles)
// ---------------------------------------------------------------------------
__global__ __launch_bounds__(256) void transposeQ_kernel(const float* __restrict__ Q) {
    __shared__ float tile[32][33];
    const int b = blockIdx.z;
    const int s0 = blockIdx.x * 32, d0 = blockIdx.y * 32;
    const int tx = threadIdx.x, ty = threadIdx.y;  // (32, 8)
    const float* src = Q + ((size_t)b * SEQ + s0) * DIM + d0;
#pragma unroll
    for (int i = 0; i < 4; i++)
        tile[ty + 8 * i][tx] = src[(size_t)(ty + 8 * i) * DIM + tx];
    __syncthreads();
    float* dst = g_Qt + ((size_t)b * DIM + d0) * SEQ + s0;
#pragma unroll
    for (int i = 0; i < 4; i++)
        dst[(size_t)(ty + 8 * i) * SEQ + tx] = tile[tx][ty + 8 * i];
}

// ===========================================================================
// Shared GEMM body (single static-smem buffer, register-prefetch) — macro so
// both GEMMs stay PLAIN kernels (no templates/dyn smem/attributes; R8 lesson).
//   D[m][n] = sum_k A[k][m]*B[k][n], tf32 split products hh+hl+lh.
//   CTA 128x128, 512 threads, 16 warps of 32x32 (R10: was 8 warps of 64x32 —
//   occ was 12.4%, tensor pipe 51.5% -> double warps/SMSP).
//   Smem pad 136 (was 132): fragment LDS now bank-conflict-free (8q+g).
// ===========================================================================
#define GEMM_BODY(NCHUNK, LDA, LDB, EPILOGUE)                                  \
    __shared__ float As[32 * 136];                                             \
    __shared__ float Bs[32 * 136];                                             \
    const int t = threadIdx.x;                                                 \
    const int wid = t >> 5, lane = t & 31;                                     \
    const int g = lane >> 2, q = lane & 3;                                     \
    const int mw = (wid >> 2) * 32;                                            \
    const int nw = (wid & 3) * 32;                                             \
    const int b = blockIdx.z;                                                  \
    const int m0 = blockIdx.y * 128;                                           \
    const int n0 = blockIdx.x * 128;                                           \
    float acc[2][4][4] = {};                                                   \
    float4 ar[2], br[2];                                                       \
    const int lrow = t >> 4, lcol = (t & 15) * 4;                              \
    /* prologue load chunk 0 */                                                \
    _Pragma("unroll")                                                          \
    for (int u = 0; u < 2; u++) {                                              \
        ar[u] = *(const float4*)&Ab[(size_t)lrow * (LDA) + m0 + lcol + u * 64]; \
        br[u] = *(const float4*)&Bb[(size_t)lrow * (LDB) + n0 + lcol + u * 64]; \
    }                                                                          \
    _Pragma("unroll")                                                          \
    for (int u = 0; u < 2; u++) {                                              \
        *(float4*)&As[lrow * 136 + lcol + u * 64] = ar[u];                     \
        *(float4*)&Bs[lrow * 136 + lcol + u * 64] = br[u];                     \
    }                                                                          \
    __syncthreads();                                                           \
    for (int c = 0; c < (NCHUNK); c++) {                                       \
        if (c + 1 < (NCHUNK)) {                                                \
            const int kn = (c + 1) * 32;                                       \
            _Pragma("unroll")                                                  \
            for (int u = 0; u < 2; u++) {                                      \
                ar[u] = *(const float4*)&Ab[(size_t)(kn + lrow) * (LDA) + m0 + lcol + u * 64]; \
                br[u] = *(const float4*)&Bb[(size_t)(kn + lrow) * (LDB) + n0 + lcol + u * 64]; \
            }                                                                  \
        }                                                                      \
        _Pragma("unroll")                                                      \
        for (int kk = 0; kk < 4; kk++) {                                       \
            uint32_t bh[8], bl[8];                                             \
            _Pragma("unroll")                                                  \
            for (int nt = 0; nt < 4; nt++) {                                   \
                float x0 = Bs[(kk * 8 + q) * 136 + nw + nt * 8 + g];           \
                float x1 = Bs[(kk * 8 + q + 4) * 136 + nw + nt * 8 + g];       \
                split_tf32(x0, bh[nt * 2 + 0], bl[nt * 2 + 0]);                \
                split_tf32(x1, bh[nt * 2 + 1], bl[nt * 2 + 1]);                \
            }                                                                  \
            uint32_t ah[2][4], al[2][4];                                       \
            _Pragma("unroll")                                                  \
            for (int mt = 0; mt < 2; mt++) {                                   \
                const float* r0 = &As[(kk * 8 + q) * 136 + mw + mt * 16 + g];  \
                const float* r1 = &As[(kk * 8 + q + 4) * 136 + mw + mt * 16 + g]; \
                split_tf32(r0[0], ah[mt][0], al[mt][0]);                       \
                split_tf32(r0[8], ah[mt][1], al[mt][1]);                       \
                split_tf32(r1[0], ah[mt][2], al[mt][2]);                       \
                split_tf32(r1[8], ah[mt][3], al[mt][3]);                       \
            }                                                                  \
            _Pragma("unroll")                                                  \
            for (int mt = 0; mt < 2; mt++)                                     \
                _Pragma("unroll")                                              \
                for (int nt = 0; nt < 4; nt++)                                 \
                    mma_tf32(acc[mt][nt], ah[mt], &bh[nt * 2]);                \
            _Pragma("unroll")                                                  \
            for (int mt = 0; mt < 2; mt++)                                     \
                _Pragma("unroll")                                              \
                for (int nt = 0; nt < 4; nt++)                                 \
                    mma_tf32(acc[mt][nt], ah[mt], &bl[nt * 2]);                \
            _Pragma("unroll")                                                  \
            for (int mt = 0; mt < 2; mt++)                                     \
                _Pragma("unroll")                                              \
                for (int nt = 0; nt < 4; nt++)                                 \
                    mma_tf32(acc[mt][nt], al[mt], &bh[nt * 2]);                \
        }                                                                      \
        __syncthreads();                                                       \
        if (c + 1 < (NCHUNK)) {                                                \
            _Pragma("unroll")                                                  \
            for (int u = 0; u < 2; u++) {                                      \
                *(float4*)&As[lrow * 136 + lcol + u * 64] = ar[u];             \
                *(float4*)&Bs[lrow * 136 + lcol + u * 64] = br[u];             \
            }                                                                  \
            __syncthreads();                                                   \
        }                                                                      \
    }                                                                          \
    _Pragma("unroll")                                                          \
    for (int mt = 0; mt < 2; mt++) {                                           \
        _Pragma("unroll")                                                      \
        for (int nt = 0; nt < 4; nt++) {                                       \
            const int m = m0 + mw + mt * 16 + g;                               \
            const int n = n0 + nw + nt * 8 + 2 * q;                            \
            EPILOGUE                                                           \
        }                                                                      \
    }

// ---------------------------------------------------------------------------
// gemmA: M[i][j] = sum_s K[s][i] V[s][j]    (k-major x k-major, K=2048)
// ---------------------------------------------------------------------------
__global__ __launch_bounds__(512, 1) void gemmA_tf32(const float* __restrict__ Kg,
                                                     const float* __restrict__ Vg) {
    const float* Ab = Kg + (size_t)blockIdx.z * SEQ * DIM;
    const float* Bb = Vg + (size_t)blockIdx.z * SEQ * DIM;
    GEMM_BODY(SEQ / 32, DIM, DIM, {
        float* dst = g_M + (size_t)b * DIM * DIM + (size_t)m * DIM + n;
        *(float2*)dst = make_float2(acc[mt][nt][0], acc[mt][nt][1]);
        *(float2*)(dst + 8 * DIM) = make_float2(acc[mt][nt][2], acc[mt][nt][3]);
    })
}

// ---------------------------------------------------------------------------
// gemmB: X[q][j] = sum_i Qt[i][q] M[i][j] / sqrt(512)   (K=512)
// ---------------------------------------------------------------------------
__global__ __launch_bounds__(512, 1) void gemmB_tf32(float* __restrict__ Og) {
    const float* Ab = g_Qt + (size_t)blockIdx.z * DIM * SEQ;
    const float* Bb = g_M + (size_t)blockIdx.z * DIM * DIM;
    GEMM_BODY(DIM / 32, SEQ, DIM, {
        const float sc = 0.044194173824159216f; /* 1/sqrt(512) */
        float* dst = Og + ((size_t)b * SEQ + m) * DIM + n;
        *(float2*)dst = make_float2(acc[mt][nt][0] * sc, acc[mt][nt][1] * sc);
        *(float2*)(dst + 8 * DIM) =
            make_float2(acc[mt][nt][2] * sc, acc[mt][nt][3] * sc);
    })
}

// ---------------------------------------------------------------------------
// PROVEN (R4) masked softmax, dtype-flexible valid_len
// ---------------------------------------------------------------------------
__global__ __launch_bounds__(128) void softmax_kernel(float* __restrict__ X,
                                                      const void* __restrict__ vlen_raw) {
    const int row = blockIdx.x;
    const int qi = row & (SEQ - 1);
    long long L = g_vlen_is64 ? ((const long long*)vlen_raw)[qi]
                              : (long long)((const int*)vlen_raw)[qi];
    float* xr = X + (size_t)row * DIM;
    const int t = threadIdx.x;
    const int j = t << 2;

    float4 v = *(float4*)&xr[j];
    float vals[4] = {v.x, v.y, v.z, v.w};
#pragma unroll
    for (int c = 0; c < 4; c++)
        if ((long long)(j + c) > L) vals[c] = -1000000.0f;

    __shared__ float red[4];
    const int lane = t & 31, warp = t >> 5;

    float m = fmaxf(fmaxf(vals[0], vals[1]), fmaxf(vals[2], vals[3]));
#pragma unroll
    for (int o = 16; o > 0; o >>= 1) m = fmaxf(m, __shfl_xor_sync(0xffffffffu, m, o));
    if (lane == 0) red[warp] = m;
    __syncthreads();
    m = fmaxf(fmaxf(red[0], red[1]), fmaxf(red[2], red[3]));
    __syncthreads();

    float e[4];
#pragma unroll
    for (int c = 0; c < 4; c++) e[c] = expf(vals[c] - m);
    float s = e[0] + e[1] + e[2] + e[3];
#pragma unroll
    for (int o = 16; o > 0; o >>= 1) s += __shfl_xor_sync(0xffffffffu, s, o);
    if (lane == 0) red[warp] = s;
    __syncthreads();
    s = red[0] + red[1] + red[2] + red[3];

    const float inv = 1.0f / s;
    *(float4*)&xr[j] = make_float4(e[0] * inv, e[1] * inv, e[2] * inv, e[3] * inv);
}

// ---------------------------------------------------------------------------
// Launch (dict order K, V, Q, valid_len — proven R4)
// ---------------------------------------------------------------------------
extern "C" void kernel_launch(void* const* d_in, const int* in_sizes, int n_in,
                              void* d_out, int out_size) {
    const float* K = (const float*)d_in[0];
    const float* V = (const float*)d_in[1];
    const float* Q = (const float*)d_in[2];
    const void* vlen = d_in[3];
    float* out = (float*)d_out;
    (void)in_sizes; (void)n_in; (void)out_size;

    detect_vlen_kernel<<<1, 256>>>((const unsigned long long*)vlen);
    transposeQ_kernel<<<dim3(SEQ / 32, DIM / 32, BATCH), dim3(32, 8)>>>(Q);

    gemmA_tf32<<<dim3(4, 4, BATCH), 512>>>(K, V);
    gemmB_tf32<<<dim3(4, 16, BATCH), 512>>>(out);

    softmax_kernel<<<BATCH * SEQ, 128>>>(out, vlen);
}